// round 8
// baseline (speedup 1.0000x reference)
#include <cuda_runtime.h>
#include <cstdint>

// ChannelExchangeWithConv: N=1, C=128, H=W=512, p=2
// Heterogeneous persistent CTAs: even blockIdx = GEMM (cp.async double-buffered),
// odd blockIdx = pure streaming copy of odd channels (keeps DRAM busy always).

#define HW    262144
#define TP    128
#define CH    64
#define WROW  68
#define NT    (HW / TP)        // 2048 tiles per direction
#define NJOBS (2 * NT)         // 4096 GEMM jobs
#define NPAIR 148
#define NCTAS (2 * NPAIR)      // 296

typedef unsigned long long u64;

__device__ __forceinline__ u64 pkdup(float x) {
    u64 r; asm("mov.b64 %0, {%1, %1};" : "=l"(r) : "f"(x)); return r;
}
__device__ __forceinline__ u64 pk2(float x, float y) {
    u64 r; asm("mov.b64 %0, {%1, %2};" : "=l"(r) : "f"(x), "f"(y)); return r;
}
__device__ __forceinline__ void unpk(u64 v, float& lo, float& hi) {
    asm("mov.b64 {%0, %1}, %2;" : "=f"(lo), "=f"(hi) : "l"(v));
}
#define FMA2(acc, a, b) \
    asm("fma.rn.f32x2 %0, %1, %2, %0;" : "+l"(acc) : "l"(a), "l"(b))

__device__ __forceinline__ void cpasync16(uint32_t s, const void* g) {
    asm volatile("cp.async.cg.shared.global [%0], [%1], 16;" :: "r"(s), "l"(g));
}

__global__ __launch_bounds__(256, 2)
void cx_kernel(const float* __restrict__ lst, const float* __restrict__ gui,
               const float* __restrict__ w1,  const float* __restrict__ b1,
               const float* __restrict__ w2,  const float* __restrict__ b2,
               float* __restrict__ out)
{
    extern __shared__ float smem[];
    const int tid = threadIdx.x;
    const int bx  = blockIdx.x;

    // ================= COPY ROLE (odd bx): stream odd channels =================
    if (bx & 1) {
        // float4 index space: [2 dirs][64 odd-ch][65536 px4]  -> 2^23 total
        const uint32_t TOTAL = 8388608u;           // 2 * 64 * 65536
        const uint32_t S     = NPAIR * 256;        // 37888 threads in copy role
        uint32_t i = (uint32_t)(bx >> 1) * 256 + tid;

        while (i + 3u * S < TOTAL) {
            uint32_t i0 = i, i1 = i + S, i2 = i + 2u * S, i3 = i + 3u * S;
            float4 v0, v1, v2, v3;
            const float* s0; float* d0; const float* s1; float* d1;
            const float* s2; float* d2; const float* s3; float* d3;
            {
                uint32_t d = i0 >> 22, r = i0 & 4194303u;
                size_t off = (size_t)(2 * (r >> 16) + 1) * HW + (size_t)(r & 65535u) * 4;
                s0 = (d ? gui : lst) + off; d0 = out + (size_t)d * 128 * HW + off;
            }
            {
                uint32_t d = i1 >> 22, r = i1 & 4194303u;
                size_t off = (size_t)(2 * (r >> 16) + 1) * HW + (size_t)(r & 65535u) * 4;
                s1 = (d ? gui : lst) + off; d1 = out + (size_t)d * 128 * HW + off;
            }
            {
                uint32_t d = i2 >> 22, r = i2 & 4194303u;
                size_t off = (size_t)(2 * (r >> 16) + 1) * HW + (size_t)(r & 65535u) * 4;
                s2 = (d ? gui : lst) + off; d2 = out + (size_t)d * 128 * HW + off;
            }
            {
                uint32_t d = i3 >> 22, r = i3 & 4194303u;
                size_t off = (size_t)(2 * (r >> 16) + 1) * HW + (size_t)(r & 65535u) * 4;
                s3 = (d ? gui : lst) + off; d3 = out + (size_t)d * 128 * HW + off;
            }
            v0 = *(const float4*)s0; v1 = *(const float4*)s1;
            v2 = *(const float4*)s2; v3 = *(const float4*)s3;
            *(float4*)d0 = v0; *(float4*)d1 = v1;
            *(float4*)d2 = v2; *(float4*)d3 = v3;
            i += 4u * S;
        }
        while (i < TOTAL) {
            uint32_t d = i >> 22, r = i & 4194303u;
            size_t off = (size_t)(2 * (r >> 16) + 1) * HW + (size_t)(r & 65535u) * 4;
            *(float4*)(out + (size_t)d * 128 * HW + off) =
                *(const float4*)((d ? gui : lst) + off);
            i += S;
        }
        return;
    }

    // ================= GEMM ROLE (even bx) =================
    float* Xbuf = smem;                         // [2][64][128] double-buffered x tiles
    float* Wt   = smem + 2 * CH * TP;           // [2][64][68]
    float* Bs   = Wt + 2 * CH * WROW;           // [2][64]

    const int gbx = bx >> 1;                    // 0..147

    // stage BOTH weight sets (transposed) + biases
    #pragma unroll
    for (int i = 0; i < 32; i++) {
        int idx = i * 256 + tid;
        int d   = idx >> 12;
        int o   = (idx >> 6) & 63;
        int c   = idx & 63;
        const float* W = d ? w1 : w2;
        Wt[(d * CH + c) * WROW + o] = W[o * CH + c];
    }
    if (tid < 2 * CH) Bs[tid] = (tid < CH) ? b2[tid] : b1[tid - CH];

    // x-tile cp.async mapping: [64 rows][32 float4 cols], 8 float4 per thread
    const int lrow = tid >> 5;
    const int lcol = (tid & 31) << 2;

    const uint32_t sX0 = (uint32_t)__cvta_generic_to_shared(Xbuf);
    const uint32_t sX1 = (uint32_t)__cvta_generic_to_shared(Xbuf + CH * TP);

    // GEMM mapping: 8 warps = 8 o-groups; thread tile 4px x 8o
    const int warp  = tid >> 5;
    const int q     = tid & 31;
    const int px    = 4 * q;
    const int obase = warp * 8;

    // prologue: prefetch job0 x-tile into buf0
    {
        int j = gbx;
        int dir = j >> 11, tile = j & (NT - 1);
        const float* xin = dir ? lst : gui;
        const float* gp  = xin + (size_t)tile * TP + lcol;
        #pragma unroll
        for (int i = 0; i < 8; i++) {
            int row = lrow + 8 * i;
            cpasync16(sX0 + (uint32_t)(row * TP + lcol) * 4, gp + (size_t)(2 * row) * HW);
        }
        asm volatile("cp.async.commit_group;");
    }

    int it = 0;
    for (int j = gbx; j < NJOBS; j += NPAIR, it++) {
        const int cur = it & 1;
        const int dir = j >> 11, tile = j & (NT - 1);
        const int pix0 = tile * TP;
        float* oo = out + (size_t)dir * 128 * HW;

        const int jn = j + NPAIR;
        if (jn < NJOBS) {
            int dn = jn >> 11, tn = jn & (NT - 1);
            const float* xinN = dn ? lst : gui;
            uint32_t sdst = cur ? sX0 : sX1;
            const float* gpN = xinN + (size_t)tn * TP + lcol;
            #pragma unroll
            for (int i = 0; i < 8; i++) {
                int row = lrow + 8 * i;
                cpasync16(sdst + (uint32_t)(row * TP + lcol) * 4, gpN + (size_t)(2 * row) * HW);
            }
            asm volatile("cp.async.commit_group;");
            asm volatile("cp.async.wait_group 1;");
        } else {
            asm volatile("cp.async.wait_group 0;");
        }
        __syncthreads();

        const float* Xs = Xbuf + cur * CH * TP;
        const float* Wd = Wt + dir * CH * WROW + obase;
        const float* Bd = Bs + dir * CH;

        u64 acc[4][4];
        #pragma unroll
        for (int jj = 0; jj < 4; jj++) {
            u64 bb = pk2(Bd[obase + 2 * jj], Bd[obase + 2 * jj + 1]);
            acc[0][jj] = bb; acc[1][jj] = bb; acc[2][jj] = bb; acc[3][jj] = bb;
        }

        const float* xp = Xs + px;

        #pragma unroll 4
        for (int c = 0; c < CH; c++) {
            float4 xv = *(const float4*)(xp + c * TP);
            u64 x0 = pkdup(xv.x), x1 = pkdup(xv.y), x2 = pkdup(xv.z), x3 = pkdup(xv.w);
            const u64* wr = (const u64*)(Wd + c * WROW);
            ulonglong2 wa = *(const ulonglong2*)(wr);
            ulonglong2 wb = *(const ulonglong2*)(wr + 2);
            u64 w[4] = {wa.x, wa.y, wb.x, wb.y};
            #pragma unroll
            for (int jj = 0; jj < 4; jj++) {
                FMA2(acc[0][jj], w[jj], x0);
                FMA2(acc[1][jj], w[jj], x1);
                FMA2(acc[2][jj], w[jj], x2);
                FMA2(acc[3][jj], w[jj], x3);
            }
        }

        // store GEMM outputs: pair jj = conv o (obase+2jj, +1) -> global ch 2*obase+4jj, +2
        #pragma unroll
        for (int jj = 0; jj < 4; jj++) {
            float a0, a1, b0v, b1v, c0, c1, d0, d1;
            unpk(acc[0][jj], a0, a1);
            unpk(acc[1][jj], b0v, b1v);
            unpk(acc[2][jj], c0, c1);
            unpk(acc[3][jj], d0, d1);
            size_t ch0 = (size_t)2 * obase + 4 * jj;
            *(float4*)(oo + ch0 * HW + pix0 + px)       = make_float4(a0, b0v, c0, d0);
            *(float4*)(oo + (ch0 + 2) * HW + pix0 + px) = make_float4(a1, b1v, c1, d1);
        }

        __syncthreads();   // all reads of buf[cur] done before refill next iter
    }
}

extern "C" void kernel_launch(void* const* d_in, const int* in_sizes, int n_in,
                              void* d_out, int out_size)
{
    const float* lst = (const float*)d_in[0];
    const float* gui = (const float*)d_in[1];
    const float* w1  = (const float*)d_in[2];
    const float* b1  = (const float*)d_in[3];
    const float* w2  = (const float*)d_in[4];
    const float* b2  = (const float*)d_in[5];
    float* out = (float*)d_out;

    const size_t smem = (size_t)2 * CH * TP * 4 + (size_t)2 * CH * WROW * 4 + 2 * CH * 4; // 100864 B
    cudaFuncSetAttribute(cx_kernel, cudaFuncAttributeMaxDynamicSharedMemorySize, (int)smem);

    cx_kernel<<<NCTAS, 256, smem>>>(lst, gui, w1, b1, w2, b2, out);
}

// round 9
// speedup vs baseline: 1.2434x; 1.2434x over previous
#include <cuda_runtime.h>
#include <cstdint>

// ChannelExchangeWithConv: N=1, C=128, H=W=512, p=2
// Warp-autonomous persistent kernel: each warp owns (dir, 16-pixel tile) jobs
// end-to-end with a private smem x-slice. No CTA barriers in the main loop.

#define HW     262144
#define CH     64
#define WPX    16                  // pixels per warp job
#define NTW    (HW / WPX)          // 16384 tiles per direction
#define NWJOBS (2 * NTW)           // 32768 warp jobs
#define NCTAS  296                 // 2 per SM
#define NWARPS (NCTAS * 8)         // 2368

typedef unsigned long long u64;

__device__ __forceinline__ u64 pkdup(float x) {
    u64 r; asm("mov.b64 %0, {%1, %1};" : "=l"(r) : "f"(x)); return r;
}
__device__ __forceinline__ u64 pk2(float x, float y) {
    u64 r; asm("mov.b64 %0, {%1, %2};" : "=l"(r) : "f"(x), "f"(y)); return r;
}
__device__ __forceinline__ void unpk(u64 v, float& lo, float& hi) {
    asm("mov.b64 {%0, %1}, %2;" : "=f"(lo), "=f"(hi) : "l"(v));
}
#define FMA2(acc, a, b) \
    asm("fma.rn.f32x2 %0, %1, %2, %0;" : "+l"(acc) : "l"(a), "l"(b))

__global__ __launch_bounds__(256, 2)
void cx_kernel(const float* __restrict__ lst, const float* __restrict__ gui,
               const float* __restrict__ w1,  const float* __restrict__ b1,
               const float* __restrict__ w2,  const float* __restrict__ b2,
               float* __restrict__ out)
{
    extern __shared__ float smem[];
    // [8 warps][64 ch][16 px] private x slices (32 KB)
    float* Slice = smem;
    // [2 dirs][64 c][64 o] transposed weights (32 KB)
    float* Wt = smem + 8 * CH * WPX;
    float* Bs = Wt + 2 * CH * CH;       // [2][64]

    const int tid  = threadIdx.x;
    const int warp = tid >> 5;
    const int lane = tid & 31;
    const int bx   = blockIdx.x;

    // --- stage both weight sets (transposed) + biases, once per CTA ---
    #pragma unroll
    for (int i = 0; i < 32; i++) {
        int idx = i * 256 + tid;      // 0..8191
        int d   = idx >> 12;
        int o   = (idx >> 6) & 63;
        int c   = idx & 63;
        const float* W = d ? w1 : w2;
        Wt[(d * CH + c) * CH + o] = W[o * CH + c];
    }
    if (tid < 2 * CH) Bs[tid] = (tid < CH) ? b2[tid] : b1[tid - CH];
    __syncthreads();    // only CTA barrier in the kernel

    float* slice = Slice + warp * (CH * WPX);

    // x-slice float4 mapping: f = i*32 + lane; row = f>>2 (ch idx), c4 = f&3
    // GEMM lane mapping: pp = lane&7 (pixel pair), g = lane>>3 (16-o group)
    const int pp = lane & 7;
    const int g  = lane >> 3;
    const int pxl = 2 * pp;

    const int gw = bx * 8 + warp;

    // --- prologue: prefetch x for job0 ---
    float4 xreg[8];
    {
        int j = gw;
        int dir = j >> 14, t = j & (NTW - 1);
        const float* xin = dir ? lst : gui;
        const float* gp = xin + (size_t)t * WPX;
        #pragma unroll
        for (int i = 0; i < 8; i++) {
            int f = i * 32 + lane;
            xreg[i] = *(const float4*)(gp + (size_t)(2 * (f >> 2)) * HW + (f & 3) * 4);
        }
    }

    for (int j = gw; j < NWJOBS; j += NWARPS) {
        const int dir = j >> 14, t = j & (NTW - 1);
        const int pix0 = t * WPX;
        const float* cpin = dir ? gui : lst;
        float* oo = out + (size_t)dir * 128 * HW;

        // commit prefetched x into my private slice
        __syncwarp();                       // prior iter's LDS reads complete
        #pragma unroll
        for (int i = 0; i < 8; i++) {
            int f = i * 32 + lane;
            *(float4*)(slice + (f >> 2) * WPX + (f & 3) * 4) = xreg[i];
        }
        __syncwarp();                       // slice visible to all lanes

        // copy batch A (odd ch rows 0..31): issue LDGs, hide behind GEMM half 1
        float4 cpv[4];
        #pragma unroll
        for (int i = 0; i < 4; i++) {
            int f = i * 32 + lane;
            cpv[i] = *(const float4*)(cpin + (size_t)(2 * (f >> 2) + 1) * HW + pix0 + (f & 3) * 4);
        }

        // prefetch x for next job (hidden behind this job's GEMM)
        const int jn = j + NWARPS;
        if (jn < NWJOBS) {
            int dn = jn >> 14, tn = jn & (NTW - 1);
            const float* xinN = dn ? lst : gui;
            const float* gpN = xinN + (size_t)tn * WPX;
            #pragma unroll
            for (int i = 0; i < 8; i++) {
                int f = i * 32 + lane;
                xreg[i] = *(const float4*)(gpN + (size_t)(2 * (f >> 2)) * HW + (f & 3) * 4);
            }
        }

        // acc init with bias: thread tile 2px x 16o (o in [16g, 16g+16))
        const float* Bd = Bs + dir * CH + g * 16;
        u64 acc[2][8];
        #pragma unroll
        for (int jj = 0; jj < 8; jj++) {
            u64 bb = pk2(Bd[2 * jj], Bd[2 * jj + 1]);
            acc[0][jj] = bb; acc[1][jj] = bb;
        }

        const float* xp = slice + pxl;
        const float* wbase = Wt + (size_t)dir * CH * CH + g * 16;

        // GEMM first half k = 0..31
        #pragma unroll 4
        for (int c = 0; c < 32; c++) {
            float2 xv = *(const float2*)(xp + c * WPX);
            u64 x0 = pkdup(xv.x), x1 = pkdup(xv.y);
            const ulonglong2* wr = (const ulonglong2*)(wbase + c * CH);
            ulonglong2 wa = wr[0], wb = wr[1], wc2 = wr[2], wd = wr[3];
            u64 w[8] = {wa.x, wa.y, wb.x, wb.y, wc2.x, wc2.y, wd.x, wd.y};
            #pragma unroll
            for (int jj = 0; jj < 8; jj++) {
                FMA2(acc[0][jj], w[jj], x0);
                FMA2(acc[1][jj], w[jj], x1);
            }
        }

        // drain copy A, issue copy B (rows 32..63)
        #pragma unroll
        for (int i = 0; i < 4; i++) {
            int f = i * 32 + lane;
            *(float4*)(oo + (size_t)(2 * (f >> 2) + 1) * HW + pix0 + (f & 3) * 4) = cpv[i];
        }
        #pragma unroll
        for (int i = 0; i < 4; i++) {
            int f = (i + 4) * 32 + lane;
            cpv[i] = *(const float4*)(cpin + (size_t)(2 * (f >> 2) + 1) * HW + pix0 + (f & 3) * 4);
        }

        // GEMM second half k = 32..63
        #pragma unroll 4
        for (int c = 32; c < CH; c++) {
            float2 xv = *(const float2*)(xp + c * WPX);
            u64 x0 = pkdup(xv.x), x1 = pkdup(xv.y);
            const ulonglong2* wr = (const ulonglong2*)(wbase + c * CH);
            ulonglong2 wa = wr[0], wb = wr[1], wc2 = wr[2], wd = wr[3];
            u64 w[8] = {wa.x, wa.y, wb.x, wb.y, wc2.x, wc2.y, wd.x, wd.y};
            #pragma unroll
            for (int jj = 0; jj < 8; jj++) {
                FMA2(acc[0][jj], w[jj], x0);
                FMA2(acc[1][jj], w[jj], x1);
            }
        }

        // drain copy B
        #pragma unroll
        for (int i = 0; i < 4; i++) {
            int f = (i + 4) * 32 + lane;
            *(float4*)(oo + (size_t)(2 * (f >> 2) + 1) * HW + pix0 + (f & 3) * 4) = cpv[i];
        }

        // epilogue: conv o-pair op = 8g + jj -> global even channels 4*op, 4*op+2
        float* ob = oo + (size_t)(g * 32) * HW + pix0 + pxl;
        #pragma unroll
        for (int jj = 0; jj < 8; jj++) {
            float e0, o0, e1, o1;
            unpk(acc[0][jj], e0, o0);   // px0: (even-o, odd-o)
            unpk(acc[1][jj], e1, o1);   // px1
            *(float2*)(ob + (size_t)(4 * jj) * HW)     = make_float2(e0, e1);
            *(float2*)(ob + (size_t)(4 * jj + 2) * HW) = make_float2(o0, o1);
        }
    }
}

extern "C" void kernel_launch(void* const* d_in, const int* in_sizes, int n_in,
                              void* d_out, int out_size)
{
    const float* lst = (const float*)d_in[0];
    const float* gui = (const float*)d_in[1];
    const float* w1  = (const float*)d_in[2];
    const float* b1  = (const float*)d_in[3];
    const float* w2  = (const float*)d_in[4];
    const float* b2  = (const float*)d_in[5];
    float* out = (float*)d_out;

    const size_t smem = (size_t)8 * CH * WPX * 4 + (size_t)2 * CH * CH * 4 + 2 * CH * 4; // 66048 B
    cudaFuncSetAttribute(cx_kernel, cudaFuncAttributeMaxDynamicSharedMemorySize, (int)smem);

    cx_kernel<<<NCTAS, 256, smem>>>(lst, gui, w1, b1, w2, b2, out);
}

// round 10
// speedup vs baseline: 1.7066x; 1.3725x over previous
#include <cuda_runtime.h>
#include <cstdint>

// ChannelExchangeWithConv: N=1, C=128, H=W=512, p=2
// R7 base (persistent, 2 CTA/SM, cp.async double-buffered x) with the
// passthrough copy + next-tile prefetch software-pipelined through the k-loop.

#define HW    262144
#define TP    128
#define CH    64
#define WROW  68
#define NT    (HW / TP)       // 2048 tiles per direction
#define NJOBS (2 * NT)        // 4096
#define NCTAS 296             // 2 per SM

typedef unsigned long long u64;

__device__ __forceinline__ u64 pkdup(float x) {
    u64 r; asm("mov.b64 %0, {%1, %1};" : "=l"(r) : "f"(x)); return r;
}
__device__ __forceinline__ u64 pk2(float x, float y) {
    u64 r; asm("mov.b64 %0, {%1, %2};" : "=l"(r) : "f"(x), "f"(y)); return r;
}
__device__ __forceinline__ void unpk(u64 v, float& lo, float& hi) {
    asm("mov.b64 {%0, %1}, %2;" : "=f"(lo), "=f"(hi) : "l"(v));
}
#define FMA2(acc, a, b) \
    asm("fma.rn.f32x2 %0, %1, %2, %0;" : "+l"(acc) : "l"(a), "l"(b))

__device__ __forceinline__ void cpasync16(uint32_t s, const void* g) {
    asm volatile("cp.async.cg.shared.global [%0], [%1], 16;" :: "r"(s), "l"(g));
}

__global__ __launch_bounds__(256, 2)
void cx_kernel(const float* __restrict__ lst, const float* __restrict__ gui,
               const float* __restrict__ w1,  const float* __restrict__ b1,
               const float* __restrict__ w2,  const float* __restrict__ b2,
               float* __restrict__ out)
{
    extern __shared__ float smem[];
    float* Xbuf = smem;                         // [2][64][128] double-buffered x tiles
    float* Wt   = smem + 2 * CH * TP;           // [2][64][68]
    float* Bs   = Wt + 2 * CH * WROW;           // [2][64]

    const int tid = threadIdx.x;
    const int bx  = blockIdx.x;

    // --- stage BOTH weight sets (transposed) + biases, once per CTA ---
    #pragma unroll
    for (int i = 0; i < 32; i++) {
        int idx = i * 256 + tid;
        int d   = idx >> 12;
        int o   = (idx >> 6) & 63;
        int c   = idx & 63;
        const float* W = d ? w1 : w2;
        Wt[(d * CH + c) * WROW + o] = W[o * CH + c];
    }
    if (tid < 2 * CH) Bs[tid] = (tid < CH) ? b2[tid] : b1[tid - CH];

    // x-tile cp.async mapping: [64 rows][32 float4 cols]; thread's i-th async
    // lands at row (tid>>5) + 8*i, col (tid&31)*4
    const int lrow = tid >> 5;
    const int lcol = (tid & 31) << 2;
    // copy mapping: thread's i-th float4 at row 8*i + (tid>>5), col (tid&31)*4
    const int crow = tid >> 5;
    const int ccol = (tid & 31) << 2;

    const uint32_t sX0 = (uint32_t)__cvta_generic_to_shared(Xbuf);
    const uint32_t sX1 = (uint32_t)__cvta_generic_to_shared(Xbuf + CH * TP);

    // GEMM mapping: 8 warps = 8 o-groups; thread tile 4px x 8o
    const int warp  = tid >> 5;
    const int q     = tid & 31;
    const int px    = 4 * q;
    const int obase = warp * 8;

    // --- prologue: prefetch job0 x-tile into buf0 ---
    {
        int j = bx;
        int dir = j >> 11, tile = j & (NT - 1);
        const float* xin = dir ? lst : gui;
        const float* gp  = xin + (size_t)tile * TP + lcol;
        #pragma unroll
        for (int i = 0; i < 8; i++) {
            cpasync16(sX0 + (uint32_t)((lrow + 8 * i) * TP + lcol) * 4,
                      gp + (size_t)(2 * (lrow + 8 * i)) * HW);
        }
        asm volatile("cp.async.commit_group;");
    }

    int it = 0;
    for (int j = bx; j < NJOBS; j += NCTAS, it++) {
        const int cur = it & 1;
        const int dir = j >> 11, tile = j & (NT - 1);
        const int pix0 = tile * TP;
        const float* cpin = dir ? gui : lst;
        float* oo = out + (size_t)dir * 128 * HW;

        asm volatile("cp.async.wait_group 0;");
        __syncthreads();

        const float* Xs = Xbuf + cur * CH * TP;
        const float* Wd = Wt + dir * CH * WROW + obase;
        const float* Bd = Bs + dir * CH;

        // next-tile prefetch params (issued spread over blocks 0..3)
        const int jn = j + NCTAS;
        const bool havenext = (jn < NJOBS);
        const int dn = jn >> 11, tn = jn & (NT - 1);
        const float* gpN = (dn ? lst : gui) + (size_t)tn * TP + lcol;
        const uint32_t sdst = cur ? sX0 : sX1;

        // acc init with bias
        u64 acc[4][4];
        #pragma unroll
        for (int jj = 0; jj < 4; jj++) {
            u64 bb = pk2(Bd[obase + 2 * jj], Bd[obase + 2 * jj + 1]);
            acc[0][jj] = bb; acc[1][jj] = bb; acc[2][jj] = bb; acc[3][jj] = bb;
        }

        const float* xp = Xs + px;
        const float* cbase = cpin + pix0 + ccol;   // + (2*row+1)*HW per row
        float*       obase2 = oo + pix0 + ccol;

        // copy pipeline preload: chunks 0,1
        float4 cpv[8];
        cpv[0] = *(const float4*)(cbase + (size_t)(2 * (0 * 8 + crow) + 1) * HW);
        cpv[1] = *(const float4*)(cbase + (size_t)(2 * (1 * 8 + crow) + 1) * HW);

        // --- k-loop: 8 blocks x 8 k, copy + prefetch threaded through ---
        #pragma unroll
        for (int b = 0; b < 8; b++) {
            if (b < 4 && havenext) {
                cpasync16(sdst + (uint32_t)((lrow + 8 * (2 * b)) * TP + lcol) * 4,
                          gpN + (size_t)(2 * (lrow + 8 * (2 * b))) * HW);
                cpasync16(sdst + (uint32_t)((lrow + 8 * (2 * b + 1)) * TP + lcol) * 4,
                          gpN + (size_t)(2 * (lrow + 8 * (2 * b + 1))) * HW);
            }
            if (b == 3 && havenext)
                asm volatile("cp.async.commit_group;");

            #pragma unroll
            for (int cc = 0; cc < 8; cc++) {
                const int c = b * 8 + cc;
                float4 xv = *(const float4*)(xp + c * TP);
                u64 x0 = pkdup(xv.x), x1 = pkdup(xv.y), x2 = pkdup(xv.z), x3 = pkdup(xv.w);
                const u64* wr = (const u64*)(Wd + c * WROW);
                ulonglong2 wa = *(const ulonglong2*)(wr);
                ulonglong2 wb = *(const ulonglong2*)(wr + 2);
                u64 w[4] = {wa.x, wa.y, wb.x, wb.y};
                #pragma unroll
                for (int jj = 0; jj < 4; jj++) {
                    FMA2(acc[0][jj], w[jj], x0);
                    FMA2(acc[1][jj], w[jj], x1);
                    FMA2(acc[2][jj], w[jj], x2);
                    FMA2(acc[3][jj], w[jj], x3);
                }
            }

            if (b < 6)
                cpv[b + 2] = *(const float4*)(cbase + (size_t)(2 * ((b + 2) * 8 + crow) + 1) * HW);
            *(float4*)(obase2 + (size_t)(2 * (b * 8 + crow) + 1) * HW) = cpv[b];
        }

        // GEMM output stores: pair jj = conv o (obase+2jj,+1) -> global ch 2*obase+4jj,+2
        #pragma unroll
        for (int jj = 0; jj < 4; jj++) {
            float a0, a1, b0v, b1v, c0, c1, d0, d1;
            unpk(acc[0][jj], a0, a1);
            unpk(acc[1][jj], b0v, b1v);
            unpk(acc[2][jj], c0, c1);
            unpk(acc[3][jj], d0, d1);
            size_t ch0 = (size_t)2 * obase + 4 * jj;
            *(float4*)(oo + ch0 * HW + pix0 + px)       = make_float4(a0, b0v, c0, d0);
            *(float4*)(oo + (ch0 + 2) * HW + pix0 + px) = make_float4(a1, b1v, c1, d1);
        }
    }
}

extern "C" void kernel_launch(void* const* d_in, const int* in_sizes, int n_in,
                              void* d_out, int out_size)
{
    const float* lst = (const float*)d_in[0];
    const float* gui = (const float*)d_in[1];
    const float* w1  = (const float*)d_in[2];
    const float* b1  = (const float*)d_in[3];
    const float* w2  = (const float*)d_in[4];
    const float* b2  = (const float*)d_in[5];
    float* out = (float*)d_out;

    const size_t smem = (size_t)2 * CH * TP * 4 + (size_t)2 * CH * WROW * 4 + 2 * CH * 4; // 100864 B
    cudaFuncSetAttribute(cx_kernel, cudaFuncAttributeMaxDynamicSharedMemorySize, (int)smem);

    cx_kernel<<<NCTAS, 256, smem>>>(lst, gui, w1, b1, w2, b2, out);
}